// round 4
// baseline (speedup 1.0000x reference)
#include <cuda_runtime.h>
#include <cuda_bf16.h>

// DecayModel: out[b,s,h] = (fwd[s] + bwd[s]) / norm[s] per (b,h) column.
// fwd[s] = sum_{k<=s} 0.5^{s-k} x[k];  bwd[s] = sum_{k>=s} 0.5^{k-s} x[k];
// norm[s] = 4 - 2^-s - 2^-(S-1-s)  (== 4.0f exactly in fp32 for 22<=s<=S-23).
//
// float4 variant: each thread owns 4 consecutive h columns (LDG.128/STG.128).
// Chunked along S with a decay halo: CHUNK=16 owned elements, HALO=16 warmup
// on each side (truncation < 2^-16, far under the 1e-3 gate).
// Forward scan register-resident (float4 fwd[16]); backward pass reconstructs
// x[t] = fwd[t] - 0.5*fwd[t-1] so x is read exactly once per owning thread.
// Neighbor chunks' halo reads hit L2 (wave-concurrent blocks share lines).

#define S_DIM 2048
#define H_DIM 1024
#define CHUNK 16
#define HALO  16
#define NCH   (S_DIM / CHUNK)   // 128
#define TPB   256               // 256 threads * 4 h = full H per block
#define SV    (H_DIM / 4)       // float4 stride per s step = 256

__device__ __forceinline__ float4 f4_fma(float4 a, float s, float4 b) {
    // a*s + b, componentwise
    return make_float4(fmaf(a.x, s, b.x), fmaf(a.y, s, b.y),
                       fmaf(a.z, s, b.z), fmaf(a.w, s, b.w));
}

__global__ __launch_bounds__(TPB, 2)
void decay_model_kernel(const float* __restrict__ x, float* __restrict__ out) {
    const int h4 = threadIdx.x;          // float4 lane along H
    const int ci = blockIdx.y;           // chunk index along S
    const int s0 = ci * CHUNK;
    const size_t base4 = (size_t)blockIdx.z * S_DIM * SV + h4;
    const float4* __restrict__ xc = reinterpret_cast<const float4*>(x) + base4;
    float4* __restrict__ oc = reinterpret_cast<float4*>(out) + base4;

    // ---- Left-halo warmup (zero contribution before s=0) ----
    float4 y = make_float4(0.f, 0.f, 0.f, 0.f);
    if (ci != 0) {
        #pragma unroll
        for (int t = 0; t < HALO; ++t)
            y = f4_fma(y, 0.5f, xc[(size_t)(s0 - HALO + t) * SV]);
    }
    const float4 y_left = y;

    // ---- Forward scan, register resident ----
    float4 fwd[CHUNK];
    #pragma unroll
    for (int t = 0; t < CHUNK; ++t) {
        y = f4_fma(y, 0.5f, xc[(size_t)(s0 + t) * SV]);
        fwd[t] = y;
    }

    // ---- Right-halo warmup ----
    float4 z = make_float4(0.f, 0.f, 0.f, 0.f);
    if (ci != NCH - 1) {
        #pragma unroll
        for (int t = HALO - 1; t >= 0; --t)
            z = f4_fma(z, 0.5f, xc[(size_t)(s0 + CHUNK + t) * SV]);
    }

    // ---- Backward scan + combine + normalize + streaming store ----
    if (ci == 0 || ci == NCH - 1) {
        // Boundary chunks: exact norm via exp2f (2 of 128 chunks).
        #pragma unroll
        for (int t = CHUNK - 1; t >= 0; --t) {
            float4 prev = (t > 0) ? fwd[t - 1] : y_left;
            float4 xv = f4_fma(prev, -0.5f, fwd[t]);
            z = f4_fma(z, 0.5f, xv);
            int s = s0 + t;
            float rn = 1.0f / (4.0f - exp2f(-(float)s)
                                    - exp2f(-(float)(S_DIM - 1 - s)));
            float4 o = make_float4((fwd[t].x + z.x) * rn, (fwd[t].y + z.y) * rn,
                                   (fwd[t].z + z.z) * rn, (fwd[t].w + z.w) * rn);
            __stcs(&oc[(size_t)s * SV], o);
        }
    } else {
        // Interior: norm == 4.0f exactly in fp32.
        #pragma unroll
        for (int t = CHUNK - 1; t >= 0; --t) {
            float4 prev = (t > 0) ? fwd[t - 1] : y_left;
            float4 xv = f4_fma(prev, -0.5f, fwd[t]);
            z = f4_fma(z, 0.5f, xv);
            float4 o = make_float4((fwd[t].x + z.x) * 0.25f, (fwd[t].y + z.y) * 0.25f,
                                   (fwd[t].z + z.z) * 0.25f, (fwd[t].w + z.w) * 0.25f);
            __stcs(&oc[(size_t)(s0 + t) * SV], o);
        }
    }
}

extern "C" void kernel_launch(void* const* d_in, const int* in_sizes, int n_in,
                              void* d_out, int out_size) {
    const float* x = (const float*)d_in[0];
    float* out = (float*)d_out;
    const int B = in_sizes[0] / (S_DIM * H_DIM);

    dim3 grid(1, NCH, B);   // (1, 128, B) = 2048 blocks of 256 threads
    decay_model_kernel<<<grid, TPB>>>(x, out);
}

// round 5
// speedup vs baseline: 1.0860x; 1.0860x over previous
#include <cuda_runtime.h>
#include <cuda_bf16.h>

// DecayModel: out[b,s,h] = (fwd[s] + bwd[s]) / norm[s] per (b,h) column.
// fwd[s] = sum_{k<=s} 0.5^{s-k} x[k];  bwd[s] = sum_{k>=s} 0.5^{k-s} x[k];
// norm[s] = 4 - 2^-s - 2^-(S-1-s)  (== 4.0f exactly in fp32 away from ends).
//
// Forward-state-carry variant: each thread owns one h column and a SPAN=128
// range of S, processed as 4 chunks of 32 with ping-pong register buffers.
// The fwd recurrence carries across chunks (no left-halo re-read per chunk);
// the next chunk's buffer doubles as the right halo for the current chunk's
// backward warmup (HALO=20, truncation < 2^-20). Each x element is loaded
// once (plus one 20-element halo at each span boundary -> 1.31x L1 reads,
// 1.0x DRAM). x reconstructed in the bwd pass via x[t] = fwd[t]-0.5*fwd[t-1].

#define S_DIM 2048
#define H_DIM 1024
#define CHUNK 32
#define SPANC 4
#define SPAN  (CHUNK * SPANC)   // 128
#define HALO  20
#define TPB   256

__device__ __forceinline__ void proc_chunk(
    float* __restrict__ oc, int cs, float& y,
    float (&cur)[CHUNK], const float (&nxt)[CHUNK], bool has_right)
{
    // ---- forward scan, in place (cur becomes fwd) ----
    const float y_in = y;
    float yy = y;
    #pragma unroll
    for (int t = 0; t < CHUNK; ++t) {
        yy = fmaf(yy, 0.5f, cur[t]);
        cur[t] = yy;
    }
    y = yy;

    // ---- backward warmup from the next chunk's raw x (right halo) ----
    float z = 0.0f;
    if (has_right) {
        #pragma unroll
        for (int t = HALO - 1; t >= 0; --t)
            z = fmaf(z, 0.5f, nxt[t]);
    }

    // ---- backward scan + combine + normalize + streaming store ----
    const bool boundary = (cs == 0) || (cs + CHUNK == S_DIM);
    if (boundary) {
        // exact norm via exp2f (only the first and last chunk of S)
        #pragma unroll
        for (int t = CHUNK - 1; t >= 0; --t) {
            float prev = (t > 0) ? cur[t - 1] : y_in;
            float xv = fmaf(-0.5f, prev, cur[t]);
            z = fmaf(z, 0.5f, xv);
            int s = cs + t;
            float rn = 1.0f / (4.0f - exp2f(-(float)s)
                                    - exp2f(-(float)(S_DIM - 1 - s)));
            __stcs(&oc[(size_t)s * H_DIM], (cur[t] + z) * rn);
        }
    } else {
        // interior: norm == 4.0f exactly in fp32
        #pragma unroll
        for (int t = CHUNK - 1; t >= 0; --t) {
            float prev = (t > 0) ? cur[t - 1] : y_in;
            float xv = fmaf(-0.5f, prev, cur[t]);
            z = fmaf(z, 0.5f, xv);
            __stcs(&oc[(size_t)(cs + t) * H_DIM], (cur[t] + z) * 0.25f);
        }
    }
}

__global__ __launch_bounds__(TPB, 2)
void decay_model_kernel(const float* __restrict__ x, float* __restrict__ out) {
    const int h  = blockIdx.x * TPB + threadIdx.x;   // h column (coalesced)
    const int s0 = blockIdx.y * SPAN;                // span start along S
    const size_t base = (size_t)blockIdx.z * S_DIM * H_DIM + h;
    const float* __restrict__ xc = x + base;
    float* __restrict__ oc = out + base;

    // ---- left-halo warmup, once per span ----
    float y = 0.0f;
    if (s0 != 0) {
        #pragma unroll
        for (int t = 0; t < HALO; ++t)
            y = fmaf(y, 0.5f, xc[(size_t)(s0 - HALO + t) * H_DIM]);
    }

    float A[CHUNK], B[CHUNK];

    // chunk 0 data
    #pragma unroll
    for (int t = 0; t < CHUNK; ++t)
        A[t] = xc[(size_t)(s0 + t) * H_DIM];

    // j=0: prefetch chunk 1 into B, process A
    #pragma unroll
    for (int t = 0; t < CHUNK; ++t)
        B[t] = xc[(size_t)(s0 + CHUNK + t) * H_DIM];
    proc_chunk(oc, s0, y, A, B, true);

    // j=1: prefetch chunk 2 into A, process B
    #pragma unroll
    for (int t = 0; t < CHUNK; ++t)
        A[t] = xc[(size_t)(s0 + 2 * CHUNK + t) * H_DIM];
    proc_chunk(oc, s0 + CHUNK, y, B, A, true);

    // j=2: prefetch chunk 3 into B, process A
    #pragma unroll
    for (int t = 0; t < CHUNK; ++t)
        B[t] = xc[(size_t)(s0 + 3 * CHUNK + t) * H_DIM];
    proc_chunk(oc, s0 + 2 * CHUNK, y, A, B, true);

    // j=3 (last in span): right halo only (from the next span), process B
    const bool last_span = (s0 + SPAN == S_DIM);
    if (!last_span) {
        #pragma unroll
        for (int t = 0; t < HALO; ++t)
            A[t] = xc[(size_t)(s0 + SPAN + t) * H_DIM];
    }
    proc_chunk(oc, s0 + 3 * CHUNK, y, B, A, !last_span);
}

extern "C" void kernel_launch(void* const* d_in, const int* in_sizes, int n_in,
                              void* d_out, int out_size) {
    const float* x = (const float*)d_in[0];
    float* out = (float*)d_out;
    const int B = in_sizes[0] / (S_DIM * H_DIM);

    dim3 grid(H_DIM / TPB, S_DIM / SPAN, B);   // (4, 16, B) = 1024 blocks
    decay_model_kernel<<<grid, TPB>>>(x, out);
}